// round 8
// baseline (speedup 1.0000x reference)
#include <cuda_runtime.h>
#include <cstdint>

#define BATCH 8
#define SEQ   1024
#define DIM   1024
#define HEADS 16
#define DH    64
#define INNER 1024
#define QKV_STRIDE (3 * INNER)

// Scratch (static device arrays: the sanctioned no-alloc workaround)
__device__ float g_qkv[(size_t)BATCH * SEQ * 3 * INNER];
__device__ float g_att[(size_t)BATCH * SEQ * INNER];

// ---------------------------------------------------------------------------
// tf32 helpers
// ---------------------------------------------------------------------------
__device__ __forceinline__ uint32_t f2t(float x) {
    uint32_t r;
    asm("cvt.rna.tf32.f32 %0, %1;" : "=r"(r) : "f"(x));
    return r;
}
__device__ __forceinline__ uint4 f2t4(float4 v) {
    return make_uint4(f2t(v.x), f2t(v.y), f2t(v.z), f2t(v.w));
}

// m16n8k8 tf32 MMA, fp32 accumulate. A row-major, B col-major.
__device__ __forceinline__ void mma8(float* c, const uint32_t* a, const uint32_t* b) {
    asm volatile(
        "mma.sync.aligned.m16n8k8.row.col.f32.tf32.tf32.f32 "
        "{%0,%1,%2,%3}, {%4,%5,%6,%7}, {%8,%9}, {%0,%1,%2,%3};\n"
        : "+f"(c[0]), "+f"(c[1]), "+f"(c[2]), "+f"(c[3])
        : "r"(a[0]), "r"(a[1]), "r"(a[2]), "r"(a[3]), "r"(b[0]), "r"(b[1]));
}

// ---------------------------------------------------------------------------
// tf32 GEMM: C = A*B (+bias). BM=BN=128, BK=32, 256 threads, 8 warps (2m x 4n),
// warp tile 64x32. A staged in XOR-swizzled fragment layout (uint4 stores,
// conflict-free frag loads). B row-major padded (LDB=136, conflict-free).
// Register-staged global prefetch, double-buffered smem, 1 sync per chunk.
// ---------------------------------------------------------------------------
#define LDB 136
#define ASZ 4096                 // 8mt * 4kb * 4reg * 32lane words
#define BSZ (32 * LDB)           // 4352 words
#define GEMM_SMEM ((2 * ASZ + 2 * BSZ) * 4)   // 67584 bytes

__global__ __launch_bounds__(256) void gemm_tf32(
    const float* __restrict__ A, const float* __restrict__ B,
    const float* __restrict__ bias, float* __restrict__ C,
    int M, int N, int K)
{
    extern __shared__ uint32_t sm[];
    uint32_t* Asb[2] = {sm, sm + ASZ};
    uint32_t* Bsb[2] = {sm + 2 * ASZ, sm + 2 * ASZ + BSZ};

    const int tid  = threadIdx.x;
    const int lane = tid & 31;
    const int warp = tid >> 5;
    const int row0 = blockIdx.y * 128;
    const int col0 = blockIdx.x * 128;

    const int wmt = (warp >> 2) * 4;   // mtile base (4 mtiles = 64 rows)
    const int wn  = (warp & 3) * 32;   // warp col base
    const int r4 = lane >> 2, c4 = lane & 3;

    float acc[4][4][4] = {};
    float4 ra[4], rb[4];

    // ---- global load into regs ----
    #define LOADG(kt) do {                                                     \
        _Pragma("unroll")                                                      \
        for (int it = 0; it < 4; it++) {                                       \
            int idx = it * 256 + tid;                                          \
            int m = idx >> 3, q = idx & 7;                                     \
            ra[it] = *(const float4*)(A + (size_t)(row0 + m) * K + (kt) + q * 4); \
            int nq = idx & 31, kr = idx >> 5;                                  \
            rb[it] = *(const float4*)(B + (size_t)((kt) + kr) * N + col0 + nq * 4); \
        } } while (0)

    // ---- store staged regs to smem buffer s (tf32 convert) ----
    #define STORES(s) do {                                                     \
        _Pragma("unroll")                                                      \
        for (int it = 0; it < 4; it++) {                                       \
            int idx = it * 256 + tid;                                          \
            int m = idx >> 3, q = idx & 7;                                     \
            int kb = q >> 1, khalf = q & 1;                                    \
            int regb = ((m >> 3) & 1) + 2 * khalf;                             \
            int word = (((m >> 4) * 4 + kb) * 4 + regb) * 32 +                 \
                       (((m & 7) * 4) ^ (q * 4));                              \
            *(uint4*)&Asb[s][word] = f2t4(ra[it]);                             \
            int nq = idx & 31, kr = idx >> 5;                                  \
            *(uint4*)&Bsb[s][kr * LDB + nq * 4] = f2t4(rb[it]);                \
        } } while (0)

    LOADG(0);
    STORES(0);
    const int nch = K / 32;

    for (int c = 0; c < nch; c++) {
        const int s = c & 1;
        __syncthreads();
        if (c + 1 < nch) LOADG((c + 1) * 32);

        const uint32_t* As = Asb[s];
        const uint32_t* Bs = Bsb[s];
        #pragma unroll
        for (int kb = 0; kb < 4; kb++) {
            uint32_t af[4][4], bf[4][2];
            const int sw0 = lane ^ (kb * 8);
            const int sw1 = lane ^ (kb * 8 + 4);
            #pragma unroll
            for (int fm = 0; fm < 4; fm++) {
                const int base = (((wmt + fm) * 4 + kb) * 4) * 32;
                af[fm][0] = As[base + sw0];
                af[fm][1] = As[base + 32 + sw0];
                af[fm][2] = As[base + 64 + sw1];
                af[fm][3] = As[base + 96 + sw1];
            }
            #pragma unroll
            for (int fn = 0; fn < 4; fn++) {
                const int n = wn + fn * 8 + r4;
                bf[fn][0] = Bs[(kb * 8 + c4) * LDB + n];
                bf[fn][1] = Bs[(kb * 8 + c4 + 4) * LDB + n];
            }
            #pragma unroll
            for (int fm = 0; fm < 4; fm++)
                #pragma unroll
                for (int fn = 0; fn < 4; fn++)
                    mma8(acc[fm][fn], af[fm], bf[fn]);
        }
        if (c + 1 < nch) STORES(s ^ 1);
    }

    // Epilogue
    #pragma unroll
    for (int fm = 0; fm < 4; fm++) {
        #pragma unroll
        for (int fn = 0; fn < 4; fn++) {
            int row = row0 + (wmt + fm) * 16 + r4;
            int col = col0 + wn + fn * 8 + c4 * 2;
            float b0 = 0.f, b1 = 0.f;
            if (bias) { b0 = bias[col]; b1 = bias[col + 1]; }
            *(float2*)&C[(size_t)row * N + col] =
                make_float2(acc[fm][fn][0] + b0, acc[fm][fn][1] + b1);
            *(float2*)&C[(size_t)(row + 8) * N + col] =
                make_float2(acc[fm][fn][2] + b0, acc[fm][fn][3] + b1);
        }
    }
    #undef LOADG
    #undef STORES
}

// ---------------------------------------------------------------------------
// Flash attention, tf32 MMA. CTA = 128 query rows of one (b,h); 8 warps,
// warp owns 16 rows x all 64 cols. Q frags in registers (loaded once).
// S stays in registers; softmax via quad shuffles; P round-trips through a
// per-warp smem fragment region (__syncwarp only). 2 syncthreads per KV tile.
// ---------------------------------------------------------------------------
#define KVPAD 68
#define ATTN_SMEM ((2 * 64 * KVPAD + 8 * 1024) * 4)   // 67584 bytes

__global__ __launch_bounds__(256) void attn_tf32(
    const float* __restrict__ qkv, float* __restrict__ out)
{
    extern __shared__ uint32_t sm[];
    uint32_t* Ksm = sm;                     // [j(64)][KVPAD] tf32  (b-frag: K[j][d])
    uint32_t* Vsm = sm + 64 * KVPAD;        // [d(64)][KVPAD] tf32  (V transposed)
    uint32_t* Psm = sm + 2 * 64 * KVPAD;    // per-warp [kb(8)][reg(4)][lane(32)]

    const int tid  = threadIdx.x;
    const int lane = tid & 31;
    const int warp = tid >> 5;
    const int r4 = lane >> 2, c4 = lane & 3;
    const int qt = blockIdx.x, h = blockIdx.y, b = blockIdx.z;
    const int qr0 = qt * 128 + warp * 16;

    const float* qbase = qkv + ((size_t)b * SEQ + qr0) * QKV_STRIDE + h * DH;
    const float* kbase = qkv + (size_t)b * SEQ * QKV_STRIDE + INNER     + h * DH;
    const float* vbase = qkv + (size_t)b * SEQ * QKV_STRIDE + 2 * INNER + h * DH;

    // Q fragments in registers, pre-scaled by 1/sqrt(Dh)=0.125
    uint32_t qf[8][4];
    #pragma unroll
    for (int kb = 0; kb < 8; kb++) {
        const int col = kb * 8 + c4;
        qf[kb][0] = f2t(0.125f * qbase[(size_t)r4 * QKV_STRIDE + col]);
        qf[kb][1] = f2t(0.125f * qbase[(size_t)(r4 + 8) * QKV_STRIDE + col]);
        qf[kb][2] = f2t(0.125f * qbase[(size_t)r4 * QKV_STRIDE + col + 4]);
        qf[kb][3] = f2t(0.125f * qbase[(size_t)(r4 + 8) * QKV_STRIDE + col + 4]);
    }

    float m0 = -3.0e38f, m1 = -3.0e38f, l0 = 0.f, l1 = 0.f;
    float o[8][4] = {};
    uint32_t* Pw = Psm + warp * 1024;

    for (int t = 0; t < 16; t++) {
        __syncthreads();   // previous tile fully consumed
        const float* kt_ = kbase + (size_t)t * 64 * QKV_STRIDE;
        const float* vt_ = vbase + (size_t)t * 64 * QKV_STRIDE;
        #pragma unroll
        for (int it = 0; it < 4; it++) {
            int idx = it * 256 + tid;
            int j = idx >> 4, dq = idx & 15;
            float4 kv = *(const float4*)(kt_ + (size_t)j * QKV_STRIDE + dq * 4);
            *(uint4*)&Ksm[j * KVPAD + dq * 4] = f2t4(kv);
            float4 vv = *(const float4*)(vt_ + (size_t)j * QKV_STRIDE + dq * 4);
            Vsm[(dq * 4 + 0) * KVPAD + j] = f2t(vv.x);
            Vsm[(dq * 4 + 1) * KVPAD + j] = f2t(vv.y);
            Vsm[(dq * 4 + 2) * KVPAD + j] = f2t(vv.z);
            Vsm[(dq * 4 + 3) * KVPAD + j] = f2t(vv.w);
        }
        __syncthreads();

        // ---- S = Q * K^T : warp's 16 rows x 64 cols, in registers ----
        float s[8][4] = {};
        #pragma unroll
        for (int kb = 0; kb < 8; kb++) {
            #pragma unroll
            for (int fn = 0; fn < 8; fn++) {
                uint32_t bb[2];
                bb[0] = Ksm[(fn * 8 + r4) * KVPAD + kb * 8 + c4];
                bb[1] = Ksm[(fn * 8 + r4) * KVPAD + kb * 8 + c4 + 4];
                mma8(s[fn], qf[kb], bb);
            }
        }

        // ---- online softmax, fully in registers (quad = one row) ----
        float mt0 = -3.0e38f, mt1 = -3.0e38f;
        #pragma unroll
        for (int fn = 0; fn < 8; fn++) {
            mt0 = fmaxf(mt0, fmaxf(s[fn][0], s[fn][1]));
            mt1 = fmaxf(mt1, fmaxf(s[fn][2], s[fn][3]));
        }
        mt0 = fmaxf(mt0, __shfl_xor_sync(0xffffffffu, mt0, 1));
        mt0 = fmaxf(mt0, __shfl_xor_sync(0xffffffffu, mt0, 2));
        mt1 = fmaxf(mt1, __shfl_xor_sync(0xffffffffu, mt1, 1));
        mt1 = fmaxf(mt1, __shfl_xor_sync(0xffffffffu, mt1, 2));
        const float mn0 = fmaxf(m0, mt0), mn1 = fmaxf(m1, mt1);
        const float al0 = __expf(m0 - mn0), al1 = __expf(m1 - mn1);
        float ls0 = 0.f, ls1 = 0.f;
        #pragma unroll
        for (int fn = 0; fn < 8; fn++) {
            s[fn][0] = __expf(s[fn][0] - mn0); ls0 += s[fn][0];
            s[fn][1] = __expf(s[fn][1] - mn0); ls0 += s[fn][1];
            s[fn][2] = __expf(s[fn][2] - mn1); ls1 += s[fn][2];
            s[fn][3] = __expf(s[fn][3] - mn1); ls1 += s[fn][3];
        }
        ls0 += __shfl_xor_sync(0xffffffffu, ls0, 1);
        ls0 += __shfl_xor_sync(0xffffffffu, ls0, 2);
        ls1 += __shfl_xor_sync(0xffffffffu, ls1, 1);
        ls1 += __shfl_xor_sync(0xffffffffu, ls1, 2);
        l0 = l0 * al0 + ls0;  l1 = l1 * al1 + ls1;
        m0 = mn0;  m1 = mn1;

        // rescale running O
        #pragma unroll
        for (int fn = 0; fn < 8; fn++) {
            o[fn][0] *= al0; o[fn][1] *= al0;
            o[fn][2] *= al1; o[fn][3] *= al1;
        }

        // ---- P c-frag -> a-frag via per-warp smem ----
        {
            const int lp0 = r4 * 4 + 2 * (c4 & 1);
            const int rb  = 2 * (c4 >> 1);
            #pragma unroll
            for (int fn = 0; fn < 8; fn++) {
                Pw[(fn * 4 + rb) * 32 + lp0]         = f2t(s[fn][0]);
                Pw[(fn * 4 + rb) * 32 + lp0 + 1]     = f2t(s[fn][1]);
                Pw[(fn * 4 + rb + 1) * 32 + lp0]     = f2t(s[fn][2]);
                Pw[(fn * 4 + rb + 1) * 32 + lp0 + 1] = f2t(s[fn][3]);
            }
        }
        __syncwarp();

        // ---- O += P * V ----
        #pragma unroll
        for (int kb = 0; kb < 8; kb++) {
            uint32_t a[4];
            a[0] = Pw[(kb * 4 + 0) * 32 + lane];
            a[1] = Pw[(kb * 4 + 1) * 32 + lane];
            a[2] = Pw[(kb * 4 + 2) * 32 + lane];
            a[3] = Pw[(kb * 4 + 3) * 32 + lane];
            #pragma unroll
            for (int fn = 0; fn < 8; fn++) {
                uint32_t bb[2];
                bb[0] = Vsm[(fn * 8 + r4) * KVPAD + kb * 8 + c4];
                bb[1] = Vsm[(fn * 8 + r4) * KVPAD + kb * 8 + c4 + 4];
                mma8(o[fn], a, bb);
            }
        }
        __syncwarp();   // P reads done before next tile's P writes
    }

    // ---- normalize and write merged-heads [B, N, INNER] ----
    const float inv0 = 1.f / l0, inv1 = 1.f / l1;
    float* ob = out + ((size_t)b * SEQ + qr0) * INNER + h * DH;
    #pragma unroll
    for (int fn = 0; fn < 8; fn++) {
        const int col = fn * 8 + 2 * c4;
        *(float2*)&ob[(size_t)r4 * INNER + col] =
            make_float2(o[fn][0] * inv0, o[fn][1] * inv0);
        *(float2*)&ob[(size_t)(r4 + 8) * INNER + col] =
            make_float2(o[fn][2] * inv1, o[fn][3] * inv1);
    }
}

// ---------------------------------------------------------------------------
// Launch
// ---------------------------------------------------------------------------
extern "C" void kernel_launch(void* const* d_in, const int* in_sizes, int n_in,
                              void* d_out, int out_size)
{
    const float* x      = (const float*)d_in[0];
    const float* w_qkv  = (const float*)d_in[1];
    const float* w_out  = (const float*)d_in[2];
    const float* b_out  = (const float*)d_in[3];
    float* out = (float*)d_out;

    float* qkv; cudaGetSymbolAddress((void**)&qkv, g_qkv);
    float* att; cudaGetSymbolAddress((void**)&att, g_att);

    const int M = BATCH * SEQ;   // 8192

    cudaFuncSetAttribute(gemm_tf32, cudaFuncAttributeMaxDynamicSharedMemorySize, GEMM_SMEM);
    cudaFuncSetAttribute(attn_tf32, cudaFuncAttributeMaxDynamicSharedMemorySize, ATTN_SMEM);

    // 1) QKV projection: [8192,1024] x [1024,3072]
    gemm_tf32<<<dim3(3 * INNER / 128, M / 128), 256, GEMM_SMEM>>>(
        x, w_qkv, nullptr, qkv, M, 3 * INNER, DIM);

    // 2) Flash attention
    attn_tf32<<<dim3(SEQ / 128, HEADS, BATCH), 256, ATTN_SMEM>>>(qkv, att);

    // 3) Output projection: [8192,1024] x [1024,1024] + bias
    gemm_tf32<<<dim3(DIM / 128, M / 128), 256, GEMM_SMEM>>>(
        att, w_out, b_out, out, M, DIM, INNER);
}